// round 3
// baseline (speedup 1.0000x reference)
#include <cuda_runtime.h>
#include <cstdint>

// WinnerTakesAll: per-batch top-64 mask. x: (32,32,256,256) fp32.
// v3: select @ 2 CTAs/SM + histogram-based merge + no memset node.

#define BATCHES 32
#define N_PER   2097152
#define TPB_A   512
#define VPT4    8                          // float4 per thread (32 elems)
#define CHUNK   (TPB_A * VPT4 * 4)         // 16384 elements
#define BPB     (N_PER / CHUNK)            // 128 blocks per batch
#define CAP     16384                      // per-batch candidate capacity

__device__ unsigned long long g_cand[BATCHES][CAP];
__device__ int g_cnt[BATCHES];             // zero-init; merge restores to 0

__device__ __forceinline__ unsigned key32(float v) {
    unsigned u = __float_as_uint(v);
    return (u & 0x80000000u) ? ~u : (u | 0x80000000u);  // order-preserving
}

// ---------------------------------------------------------------------------
// Kernel A: one streaming read; per-block threshold (pool of 128 warp-top-8
// maxes => >=64 elements >= P => block top-64 subset of candidates);
// ballot-aggregated candidate emit; zero-write own output chunk.
// ---------------------------------------------------------------------------
__global__ void __launch_bounds__(TPB_A, 2)
select_kernel(const float4* __restrict__ x4, float4* __restrict__ out4) {
    __shared__ float s_pool[128];
    __shared__ float s_P;

    const int t = threadIdx.x;
    const int lane = t & 31;
    const int warp = t >> 5;
    const int batch = blockIdx.y;
    const int blk = blockIdx.x;
    const size_t base4 = (size_t)batch * (N_PER / 4) + (size_t)blk * (CHUNK / 4);

    float4 v[VPT4];
#pragma unroll
    for (int i = 0; i < VPT4; i++)
        v[i] = x4[base4 + (size_t)i * TPB_A + t];

    float tmax = __int_as_float(0xff800000);
#pragma unroll
    for (int i = 0; i < VPT4; i++)
        tmax = fmaxf(tmax, fmaxf(fmaxf(v[i].x, v[i].y), fmaxf(v[i].z, v[i].w)));

    // Warp bitonic sort (descending) of 32 thread-maxes.
    float s = tmax;
#pragma unroll
    for (int k = 2; k <= 32; k <<= 1) {
#pragma unroll
        for (int j = k >> 1; j > 0; j >>= 1) {
            float o = __shfl_xor_sync(0xffffffffu, s, j);
            bool up = ((lane & k) == 0);
            bool lower = ((lane & j) == 0);
            s = (up == lower) ? fmaxf(s, o) : fminf(s, o);
        }
    }
    if (lane < 8) s_pool[warp * 8 + lane] = s;
    __syncthreads();

    // P = 64th largest of the 128-entry pool.
    if (t < 128) {
        float p = s_pool[t];
        int r = 0;
#pragma unroll 8
        for (int j = 0; j < 128; j++) {
            float pj = s_pool[j];
            r += (pj > p) || (pj == p && j < t);
        }
        if (r == 63) s_P = p;
    }
    __syncthreads();
    const float P = s_P;

    // Candidate emit (ballot-aggregated global atomics).
#pragma unroll
    for (int i = 0; i < VPT4; i++) {
        float vv[4] = {v[i].x, v[i].y, v[i].z, v[i].w};
#pragma unroll
        for (int c = 0; c < 4; c++) {
            bool pred = (vv[c] >= P);
            unsigned m = __ballot_sync(0xffffffffu, pred);
            if (m) {
                int leader = __ffs(m) - 1;
                int pos = 0;
                if (lane == leader)
                    pos = atomicAdd(&g_cnt[batch], __popc(m));
                pos = __shfl_sync(0xffffffffu, pos, leader);
                if (pred) {
                    int my = pos + __popc(m & ((1u << lane) - 1u));
                    if (my < CAP) {
                        unsigned e = (unsigned)(blk * CHUNK + (i * TPB_A + t) * 4 + c);
                        g_cand[batch][my] =
                            ((unsigned long long)key32(vv[c]) << 32) | (unsigned)(~e);
                    }
                }
            }
        }
    }

    // Zero-write this block's output chunk.
    float4 z = make_float4(0.f, 0.f, 0.f, 0.f);
#pragma unroll
    for (int i = 0; i < VPT4; i++)
        out4[base4 + (size_t)i * TPB_A + t] = z;
}

// ---------------------------------------------------------------------------
// Kernel M: per-batch exact top-64 via 12-bit histogram threshold,
// compact + exact rank, scatter winners, restore g_cnt to 0.
// ---------------------------------------------------------------------------
#define TPB_M 512
#define NBINS 4096
#define BINS_PER_T (NBINS / TPB_M)   // 8
#define MAXS  512
__global__ void __launch_bounds__(TPB_M)
merge_kernel(const float* __restrict__ x, float* __restrict__ out) {
    __shared__ int s_hist[NBINS];              // 16 KiB
    __shared__ int s_part[TPB_M];              // suffix-scan workspace
    __shared__ unsigned long long s_surv[MAXS];
    __shared__ int s_b;                        // threshold bin
    __shared__ int s_scnt;

    const int t = threadIdx.x;
    const int batch = blockIdx.x;
    const int cnt = min(g_cnt[batch], CAP);

#pragma unroll
    for (int i = 0; i < BINS_PER_T; i++) s_hist[t * BINS_PER_T + i] = 0;
    if (t == 0) s_scnt = 0;
    __syncthreads();

    // Histogram of top-12 key bits (candidates are L2-resident).
    for (int i = t; i < cnt; i += TPB_M) {
        unsigned k = (unsigned)(g_cand[batch][i] >> 32);
        atomicAdd(&s_hist[k >> 20], 1);
    }
    __syncthreads();

    // Per-thread group sum (8 bins), then inclusive suffix scan over groups.
    int local = 0;
#pragma unroll
    for (int i = 0; i < BINS_PER_T; i++) local += s_hist[t * BINS_PER_T + i];
    s_part[t] = local;
    __syncthreads();
    for (int off = 1; off < TPB_M; off <<= 1) {
        int add = (t + off < TPB_M) ? s_part[t + off] : 0;
        __syncthreads();
        s_part[t] += add;
        __syncthreads();
    }
    // s_part[g] = count of keys in bins [g*8, NBINS). Non-increasing in g.
    // Largest group g with s_part[g] >= 64:
    if (s_part[t] >= 64 && (t == TPB_M - 1 || s_part[t + 1] < 64)) {
        // Walk bins inside group g from the top to find threshold bin b.
        int c = (t == TPB_M - 1) ? 0 : s_part[t + 1];
        int b = t * BINS_PER_T;
        for (int bin = t * BINS_PER_T + BINS_PER_T - 1; bin >= t * BINS_PER_T; bin--) {
            c += s_hist[bin];
            if (c >= 64) { b = bin; break; }
        }
        s_b = b;
    }
    __syncthreads();
    const unsigned bthr = (unsigned)s_b;

    // Compact survivors: all keys whose top-12 bits >= threshold bin.
    for (int i = t; i < cnt; i += TPB_M) {
        unsigned long long ck = g_cand[batch][i];
        if (((unsigned)(ck >> 32) >> 20) >= bthr) {
            int p = atomicAdd(&s_scnt, 1);
            if (p < MAXS) s_surv[p] = ck;
        }
    }
    __syncthreads();
    const int S = min(s_scnt, MAXS);

    // Exact rank on packed key (value desc, index asc via ~idx).
    if (t < S) {
        unsigned long long me = s_surv[t];
        int r = 0;
        for (int j = 0; j < S; j++) r += (s_surv[j] > me);
        if (r < 64) {
            unsigned idx = ~((unsigned)me);
            size_t gi = (size_t)batch * N_PER + idx;
            out[gi] = x[gi];
        }
    }

    if (t == 0) g_cnt[batch] = 0;   // restore for next (graph replay) launch
}

// ---------------------------------------------------------------------------
extern "C" void kernel_launch(void* const* d_in, const int* in_sizes, int n_in,
                              void* d_out, int out_size) {
    const float* x = (const float*)d_in[0];
    float* out = (float*)d_out;

    dim3 gA(BPB, BATCHES);
    select_kernel<<<gA, TPB_A>>>((const float4*)x, (float4*)out);
    merge_kernel<<<BATCHES, TPB_M>>>(x, out);
}

// round 4
// speedup vs baseline: 1.1572x; 1.1572x over previous
#include <cuda_runtime.h>
#include <cstdint>

// WinnerTakesAll: per-batch top-64 mask. x: (32,32,256,256) fp32.
// v4: sampled-threshold -> barrier-free streaming select -> histogram merge.

#define BATCHES 32
#define N_PER   2097152
#define N4      (N_PER / 4)            // 524288 float4 per batch

// --- sampling ---
#define SAMPLE_STRIDE 64               // every 64th float4 (1/64 of data)
#define NSAMP4  (N4 / SAMPLE_STRIDE)   // 8192 float4 samples per batch
#define TPB_S   1024
#define SAMP_PER_T (NSAMP4 / TPB_S)    // 8
#define SRANK   64                     // >=64 samples above threshold => guarantee

// --- select ---
#define TPB_A   256
#define VPT4    8
#define CHUNK4  (TPB_A * VPT4)         // 2048 float4 per block
#define BPB     (N4 / CHUNK4)          // 256 blocks per batch
#define CAP     32768                  // per-batch candidate capacity (E ~ 4096)

// --- merge ---
#define TPB_M   512
#define NBINS   4096
#define MAXS    1024

__device__ unsigned long long g_cand[BATCHES][CAP];
__device__ int g_cnt[BATCHES];         // zero-init; merge restores to 0
__device__ int g_bin[BATCHES];         // threshold bin (overwritten each run)

__device__ __forceinline__ unsigned key32(float v) {
    unsigned u = __float_as_uint(v);
    return (u & 0x80000000u) ? ~u : (u | 0x80000000u);  // order-preserving bijection
}
__device__ __forceinline__ float unkey(unsigned k) {
    return (k & 0x80000000u) ? __uint_as_float(k & 0x7fffffffu)
                             : __uint_as_float(~k);
}

// ---------------------------------------------------------------------------
// Kernel S: per-batch sampled threshold.
// Histogram top-12 key bits of 32768 sampled elements; pick largest bin edge
// with >=SRANK samples at-or-above. Those samples are real elements, so
// count(batch >= T) >= 64 unconditionally.
// ---------------------------------------------------------------------------
__global__ void __launch_bounds__(TPB_S)
sample_kernel(const float4* __restrict__ x4) {
    __shared__ int hist[NBINS];
    __shared__ int s_wsum[TPB_S / 32];
    __shared__ int s_woff[TPB_S / 32];

    const int t = threadIdx.x, lane = t & 31, warp = t >> 5;
    const int batch = blockIdx.x;

    for (int i = t; i < NBINS; i += TPB_S) hist[i] = 0;
    __syncthreads();

    const float4* xb = x4 + (size_t)batch * N4;
#pragma unroll
    for (int k = 0; k < SAMP_PER_T; k++) {
        float4 v = __ldg(&xb[(size_t)(k * TPB_S + t) * SAMPLE_STRIDE]);
        atomicAdd(&hist[key32(v.x) >> 20], 1);
        atomicAdd(&hist[key32(v.y) >> 20], 1);
        atomicAdd(&hist[key32(v.z) >> 20], 1);
        atomicAdd(&hist[key32(v.w) >> 20], 1);
    }
    __syncthreads();

    // Block-wide inclusive suffix scan over 4-bin groups (shfl-based).
    int local = 0;
#pragma unroll
    for (int i = 0; i < 4; i++) local += hist[t * 4 + i];
    int suf = local;
#pragma unroll
    for (int off = 1; off < 32; off <<= 1) {
        int o = __shfl_down_sync(0xffffffffu, suf, off);
        if (lane + off < 32) suf += o;
    }
    if (lane == 0) s_wsum[warp] = suf;
    __syncthreads();
    if (warp == 0) {
        int wv = s_wsum[lane];
        int ws = wv;
#pragma unroll
        for (int off = 1; off < 32; off <<= 1) {
            int o = __shfl_down_sync(0xffffffffu, ws, off);
            if (lane + off < 32) ws += o;
        }
        s_woff[lane] = ws - wv;   // exclusive suffix (groups above this warp)
    }
    __syncthreads();

    int suffix = suf + s_woff[warp];     // samples in bins >= 4t
    int above  = suffix - local;         // samples in bins >= 4(t+1)
    if (suffix >= SRANK && above < SRANK) {
        int c = above, b = t * 4;
        for (int bin = t * 4 + 3; bin >= t * 4; bin--) {
            c += hist[bin];
            if (c >= SRANK) { b = bin; break; }
        }
        g_bin[batch] = b;
    }
}

// ---------------------------------------------------------------------------
// Kernel A: barrier-free stream. Read x, emit candidates >= T, write zeros.
// ---------------------------------------------------------------------------
__global__ void __launch_bounds__(TPB_A)
select_kernel(const float4* __restrict__ x4, float4* __restrict__ out4) {
    const int t = threadIdx.x, lane = t & 31;
    const int batch = blockIdx.y, blk = blockIdx.x;

    const int bin = g_bin[batch];
    const unsigned K = (unsigned)bin << 20;
    // bins < 8 map to NaN patterns under unkey; fall back to -inf (accept all).
    const float Tf = (bin < 8) ? __int_as_float(0xff800000) : unkey(K);

    const size_t base4 = (size_t)batch * N4 + (size_t)blk * CHUNK4;
    const unsigned ebase = (unsigned)(blk * CHUNK4) * 4u;
    const float4 z = make_float4(0.f, 0.f, 0.f, 0.f);

#pragma unroll
    for (int i = 0; i < VPT4; i++) {
        float4 v = __ldcs(&x4[base4 + i * TPB_A + t]);
        float m4 = fmaxf(fmaxf(v.x, v.y), fmaxf(v.z, v.w));
        if (__ballot_sync(0xffffffffu, m4 >= Tf)) {       // ~23% of warp-iters
            float vv[4] = {v.x, v.y, v.z, v.w};
#pragma unroll
            for (int c = 0; c < 4; c++) {
                bool pred = (vv[c] >= Tf);
                unsigned m = __ballot_sync(0xffffffffu, pred);
                if (m) {
                    int leader = __ffs(m) - 1;
                    int pos = 0;
                    if (lane == leader)
                        pos = atomicAdd(&g_cnt[batch], __popc(m));
                    pos = __shfl_sync(0xffffffffu, pos, leader);
                    if (pred) {
                        int my = pos + __popc(m & ((1u << lane) - 1u));
                        if (my < CAP) {
                            unsigned e = ebase + (unsigned)(i * TPB_A + t) * 4u + (unsigned)c;
                            g_cand[batch][my] =
                                ((unsigned long long)key32(vv[c]) << 32) | (unsigned)(~e);
                        }
                    }
                }
            }
        }
        __stcs(&out4[base4 + i * TPB_A + t], z);
    }
}

// ---------------------------------------------------------------------------
// Kernel M: per-batch exact top-64 from candidates; scatter; reset counter.
// ---------------------------------------------------------------------------
__global__ void __launch_bounds__(TPB_M)
merge_kernel(const float* __restrict__ x, float* __restrict__ out) {
    __shared__ int hist[NBINS];
    __shared__ int s_wsum[TPB_M / 32];
    __shared__ int s_woff[TPB_M / 32];
    __shared__ unsigned long long s_surv[MAXS];
    __shared__ int s_scnt;
    __shared__ unsigned s_bin;
    __shared__ int s_tot;

    const int t = threadIdx.x, lane = t & 31, warp = t >> 5;
    const int batch = blockIdx.x;
    const int raw = g_cnt[batch];
    const int cnt = min(raw, CAP);

    if (t == 0) s_scnt = 0;

    if (raw <= CAP) {
        // ---- primary path: histogram threshold over candidates ----
        for (int i = t; i < NBINS; i += TPB_M) hist[i] = 0;
        __syncthreads();
        for (int i = t; i < cnt; i += TPB_M)
            atomicAdd(&hist[(unsigned)(g_cand[batch][i] >> 52)], 1);
        __syncthreads();

        int local = 0;
#pragma unroll
        for (int i = 0; i < 8; i++) local += hist[t * 8 + i];
        int suf = local;
#pragma unroll
        for (int off = 1; off < 32; off <<= 1) {
            int o = __shfl_down_sync(0xffffffffu, suf, off);
            if (lane + off < 32) suf += o;
        }
        if (lane == 0) s_wsum[warp] = suf;
        __syncthreads();
        if (warp == 0 && lane < TPB_M / 32) {
            int wv = s_wsum[lane];
            int ws = wv;
#pragma unroll
            for (int off = 1; off < TPB_M / 32; off <<= 1) {
                int o = __shfl_down_sync(0xffffu, ws, off);
                if (lane + off < TPB_M / 32) ws += o;
            }
            s_woff[lane] = ws - wv;
        }
        __syncthreads();
        int suffix = suf + s_woff[warp];
        int above  = suffix - local;
        if (suffix >= 64 && above < 64) {
            int c = above, b = t * 8;
            for (int bin = t * 8 + 7; bin >= t * 8; bin--) {
                c += hist[bin];
                if (c >= 64) { b = bin; break; }
            }
            s_bin = (unsigned)b;
        }
        __syncthreads();
        const unsigned bthr = s_bin;

        for (int i = t; i < cnt; i += TPB_M) {
            unsigned long long ck = g_cand[batch][i];
            if ((unsigned)(ck >> 52) >= bthr) {
                int p = atomicAdd(&s_scnt, 1);
                if (p < MAXS) s_surv[p] = ck;
            }
        }
        __syncthreads();
    } else {
        // ---- fallback (never taken for sane data): exact bitwise search on x ----
        __syncthreads();
        const float* xb = x + (size_t)batch * N_PER;
        unsigned T = 0;
        for (int bit = 31; bit >= 0; bit--) {
            unsigned candT = T | (1u << bit);
            int c = 0;
            for (int i = t; i < N_PER; i += TPB_M) c += (key32(xb[i]) >= candT);
#pragma unroll
            for (int o = 16; o > 0; o >>= 1) c += __shfl_xor_sync(0xffffffffu, c, o);
            if (lane == 0) s_wsum[warp] = c;
            __syncthreads();
            if (t == 0) {
                int tot = 0;
                for (int w = 0; w < TPB_M / 32; w++) tot += s_wsum[w];
                s_tot = tot;
            }
            __syncthreads();
            if (s_tot >= 64) T = candT;
            __syncthreads();
        }
        for (int i = t; i < N_PER; i += TPB_M) {
            unsigned u = key32(xb[i]);
            if (u >= T) {
                int p = atomicAdd(&s_scnt, 1);
                if (p < MAXS)
                    s_surv[p] = ((unsigned long long)u << 32) | (unsigned)(~i);
            }
        }
        __syncthreads();
    }

    // ---- common tail: exact rank on (value desc, index asc), scatter ----
    const int S = min(s_scnt, MAXS);
    if (t < S) {
        unsigned long long me = s_surv[t];
        int r = 0;
        for (int j = 0; j < S; j++) r += (s_surv[j] > me);
        if (r < 64) {
            unsigned idx = ~((unsigned)me);
            out[(size_t)batch * N_PER + idx] = unkey((unsigned)(me >> 32));
        }
    }
    __syncthreads();
    if (t == 0) g_cnt[batch] = 0;   // restore for next graph replay
}

// ---------------------------------------------------------------------------
extern "C" void kernel_launch(void* const* d_in, const int* in_sizes, int n_in,
                              void* d_out, int out_size) {
    const float* x = (const float*)d_in[0];
    float* out = (float*)d_out;

    sample_kernel<<<BATCHES, TPB_S>>>((const float4*)x);

    dim3 gA(BPB, BATCHES);
    select_kernel<<<gA, TPB_A>>>((const float4*)x, (float4*)out);

    merge_kernel<<<BATCHES, TPB_M>>>(x, out);
}

// round 5
// speedup vs baseline: 1.2077x; 1.0436x over previous
#include <cuda_runtime.h>
#include <cstdint>

// WinnerTakesAll: per-batch top-64 mask. x: (32,32,256,256) fp32.
// v5: coalesced sampled-threshold -> phase-separated streaming select
//     (front-batched loads, MLP=8) -> histogram merge.

#define BATCHES 32
#define N_PER   2097152
#define N4      (N_PER / 4)            // 524288 float4 per batch

// --- sampling: contiguous 32768-element prefix per batch ---
#define TPB_S   1024
#define SAMP4   8192                   // float4 sampled per batch (128 KiB)
#define SAMP_PER_T (SAMP4 / TPB_S)     // 8
#define SRANK   64

// --- select ---
#define TPB_A   256
#define VPT4    8
#define CHUNK4  (TPB_A * VPT4)         // 2048 float4 per block
#define BPB     (N4 / CHUNK4)          // 256 blocks per batch
#define CAP     32768                  // per-batch candidate capacity (E ~ 4096)

// --- merge ---
#define TPB_M   512
#define NBINS   4096
#define MAXS    1024

__device__ unsigned long long g_cand[BATCHES][CAP];
__device__ int g_cnt[BATCHES];         // zero-init; merge restores to 0
__device__ int g_bin[BATCHES];

__device__ __forceinline__ unsigned key32(float v) {
    unsigned u = __float_as_uint(v);
    return (u & 0x80000000u) ? ~u : (u | 0x80000000u);  // order-preserving
}
__device__ __forceinline__ float unkey(unsigned k) {
    return (k & 0x80000000u) ? __uint_as_float(k & 0x7fffffffu)
                             : __uint_as_float(~k);
}

// ---------------------------------------------------------------------------
// Kernel S: threshold from a contiguous sample (any real subset gives the
// unconditional guarantee: >=SRANK samples >= T  =>  >=64 batch elems >= T).
// ---------------------------------------------------------------------------
__global__ void __launch_bounds__(TPB_S)
sample_kernel(const float4* __restrict__ x4) {
    __shared__ int hist[NBINS];
    __shared__ int s_wsum[TPB_S / 32];
    __shared__ int s_woff[TPB_S / 32];

    const int t = threadIdx.x, lane = t & 31, warp = t >> 5;
    const int batch = blockIdx.x;

    for (int i = t; i < NBINS; i += TPB_S) hist[i] = 0;
    __syncthreads();

    const float4* xb = x4 + (size_t)batch * N4;
    float4 v[SAMP_PER_T];
#pragma unroll
    for (int k = 0; k < SAMP_PER_T; k++)
        v[k] = __ldg(&xb[k * TPB_S + t]);            // coalesced 128 KiB prefix
#pragma unroll
    for (int k = 0; k < SAMP_PER_T; k++) {
        atomicAdd(&hist[key32(v[k].x) >> 20], 1);
        atomicAdd(&hist[key32(v[k].y) >> 20], 1);
        atomicAdd(&hist[key32(v[k].z) >> 20], 1);
        atomicAdd(&hist[key32(v[k].w) >> 20], 1);
    }
    __syncthreads();

    // Inclusive suffix scan over 4-bin groups.
    int local = 0;
#pragma unroll
    for (int i = 0; i < 4; i++) local += hist[t * 4 + i];
    int suf = local;
#pragma unroll
    for (int off = 1; off < 32; off <<= 1) {
        int o = __shfl_down_sync(0xffffffffu, suf, off);
        if (lane + off < 32) suf += o;
    }
    if (lane == 0) s_wsum[warp] = suf;
    __syncthreads();
    if (warp == 0) {
        int wv = s_wsum[lane], ws = wv;
#pragma unroll
        for (int off = 1; off < 32; off <<= 1) {
            int o = __shfl_down_sync(0xffffffffu, ws, off);
            if (lane + off < 32) ws += o;
        }
        s_woff[lane] = ws - wv;
    }
    __syncthreads();

    int suffix = suf + s_woff[warp];
    int above  = suffix - local;
    if (suffix >= SRANK && above < SRANK) {
        int c = above, b = t * 4;
        for (int bin = t * 4 + 3; bin >= t * 4; bin--) {
            c += hist[bin];
            if (c >= SRANK) { b = bin; break; }
        }
        g_bin[batch] = b;
    }
}

// ---------------------------------------------------------------------------
// Kernel A: phase-separated stream.
//   Phase 1: 8 front-batched loads.  Phase 2: 8 independent zero stores
//   (fill the load-latency shadow).  Phase 3: candidate emit from registers.
// ---------------------------------------------------------------------------
__global__ void __launch_bounds__(TPB_A)
select_kernel(const float4* __restrict__ x4, float4* __restrict__ out4) {
    const int t = threadIdx.x, lane = t & 31;
    const int batch = blockIdx.y, blk = blockIdx.x;

    const int bin = g_bin[batch];
    const float Tf = (bin < 8) ? __int_as_float(0xff800000)
                               : unkey((unsigned)bin << 20);

    const size_t base4 = (size_t)batch * N4 + (size_t)blk * CHUNK4;
    const unsigned ebase = (unsigned)(blk * CHUNK4) * 4u;

    // Phase 1: all loads in flight.
    float4 v[VPT4];
#pragma unroll
    for (int i = 0; i < VPT4; i++)
        v[i] = __ldcs(&x4[base4 + i * TPB_A + t]);

    // Phase 2: zero stores (no dependence on loads).
    const float4 z = make_float4(0.f, 0.f, 0.f, 0.f);
#pragma unroll
    for (int i = 0; i < VPT4; i++)
        __stcs(&out4[base4 + i * TPB_A + t], z);

    // Phase 3: candidate processing from registers.
#pragma unroll
    for (int i = 0; i < VPT4; i++) {
        float m4 = fmaxf(fmaxf(v[i].x, v[i].y), fmaxf(v[i].z, v[i].w));
        if (__ballot_sync(0xffffffffu, m4 >= Tf)) {
            float vv[4] = {v[i].x, v[i].y, v[i].z, v[i].w};
#pragma unroll
            for (int c = 0; c < 4; c++) {
                bool pred = (vv[c] >= Tf);
                unsigned m = __ballot_sync(0xffffffffu, pred);
                if (m) {
                    int leader = __ffs(m) - 1;
                    int pos = 0;
                    if (lane == leader)
                        pos = atomicAdd(&g_cnt[batch], __popc(m));
                    pos = __shfl_sync(0xffffffffu, pos, leader);
                    if (pred) {
                        int my = pos + __popc(m & ((1u << lane) - 1u));
                        if (my < CAP) {
                            unsigned e = ebase + (unsigned)(i * TPB_A + t) * 4u + (unsigned)c;
                            g_cand[batch][my] =
                                ((unsigned long long)key32(vv[c]) << 32) | (unsigned)(~e);
                        }
                    }
                }
            }
        }
    }
}

// ---------------------------------------------------------------------------
// Kernel M: per-batch exact top-64 from candidates; scatter; reset counter.
// ---------------------------------------------------------------------------
__global__ void __launch_bounds__(TPB_M)
merge_kernel(const float* __restrict__ x, float* __restrict__ out) {
    __shared__ int hist[NBINS];
    __shared__ int s_wsum[TPB_M / 32];
    __shared__ int s_woff[TPB_M / 32];
    __shared__ unsigned long long s_surv[MAXS];
    __shared__ int s_scnt;
    __shared__ unsigned s_bin;
    __shared__ int s_tot;

    const int t = threadIdx.x, lane = t & 31, warp = t >> 5;
    const int batch = blockIdx.x;
    const int raw = g_cnt[batch];
    const int cnt = min(raw, CAP);

    if (t == 0) s_scnt = 0;

    if (raw <= CAP) {
        for (int i = t; i < NBINS; i += TPB_M) hist[i] = 0;
        __syncthreads();
        for (int i = t; i < cnt; i += TPB_M)
            atomicAdd(&hist[(unsigned)(g_cand[batch][i] >> 52)], 1);
        __syncthreads();

        int local = 0;
#pragma unroll
        for (int i = 0; i < 8; i++) local += hist[t * 8 + i];
        int suf = local;
#pragma unroll
        for (int off = 1; off < 32; off <<= 1) {
            int o = __shfl_down_sync(0xffffffffu, suf, off);
            if (lane + off < 32) suf += o;
        }
        if (lane == 0) s_wsum[warp] = suf;
        __syncthreads();
        if (warp == 0 && lane < TPB_M / 32) {
            int wv = s_wsum[lane], ws = wv;
#pragma unroll
            for (int off = 1; off < TPB_M / 32; off <<= 1) {
                int o = __shfl_down_sync(0xffffu, ws, off);
                if (lane + off < TPB_M / 32) ws += o;
            }
            s_woff[lane] = ws - wv;
        }
        __syncthreads();
        int suffix = suf + s_woff[warp];
        int above  = suffix - local;
        if (suffix >= 64 && above < 64) {
            int c = above, b = t * 8;
            for (int bin = t * 8 + 7; bin >= t * 8; bin--) {
                c += hist[bin];
                if (c >= 64) { b = bin; break; }
            }
            s_bin = (unsigned)b;
        }
        __syncthreads();
        const unsigned bthr = s_bin;

        for (int i = t; i < cnt; i += TPB_M) {
            unsigned long long ck = g_cand[batch][i];
            if ((unsigned)(ck >> 52) >= bthr) {
                int p = atomicAdd(&s_scnt, 1);
                if (p < MAXS) s_surv[p] = ck;
            }
        }
        __syncthreads();
    } else {
        // Fallback (only if CAP overflow): exact bitwise search over x.
        __syncthreads();
        const float* xb = x + (size_t)batch * N_PER;
        unsigned T = 0;
        for (int bit = 31; bit >= 0; bit--) {
            unsigned candT = T | (1u << bit);
            int c = 0;
            for (int i = t; i < N_PER; i += TPB_M) c += (key32(xb[i]) >= candT);
#pragma unroll
            for (int o = 16; o > 0; o >>= 1) c += __shfl_xor_sync(0xffffffffu, c, o);
            if (lane == 0) s_wsum[warp] = c;
            __syncthreads();
            if (t == 0) {
                int tot = 0;
                for (int w = 0; w < TPB_M / 32; w++) tot += s_wsum[w];
                s_tot = tot;
            }
            __syncthreads();
            if (s_tot >= 64) T = candT;
            __syncthreads();
        }
        for (int i = t; i < N_PER; i += TPB_M) {
            unsigned u = key32(xb[i]);
            if (u >= T) {
                int p = atomicAdd(&s_scnt, 1);
                if (p < MAXS)
                    s_surv[p] = ((unsigned long long)u << 32) | (unsigned)(~i);
            }
        }
        __syncthreads();
    }

    const int S = min(s_scnt, MAXS);
    if (t < S) {
        unsigned long long me = s_surv[t];
        int r = 0;
        for (int j = 0; j < S; j++) r += (s_surv[j] > me);
        if (r < 64) {
            unsigned idx = ~((unsigned)me);
            out[(size_t)batch * N_PER + idx] = unkey((unsigned)(me >> 32));
        }
    }
    __syncthreads();
    if (t == 0) g_cnt[batch] = 0;
}

// ---------------------------------------------------------------------------
extern "C" void kernel_launch(void* const* d_in, const int* in_sizes, int n_in,
                              void* d_out, int out_size) {
    const float* x = (const float*)d_in[0];
    float* out = (float*)d_out;

    sample_kernel<<<BATCHES, TPB_S>>>((const float4*)x);

    dim3 gA(BPB, BATCHES);
    select_kernel<<<gA, TPB_A>>>((const float4*)x, (float4*)out);

    merge_kernel<<<BATCHES, TPB_M>>>(x, out);
}